// round 15
// baseline (speedup 1.0000x reference)
#include <cuda_runtime.h>
#include <cuda_fp16.h>
#include <cstdint>

#define CIN  1024
#define COUT 1024
#define MAX_M 16384

// ---------------- device global scratch (allocation-free) ----------------
// g_W is zero-initialized at module load; convert_W_kernel re-zeroes it
// after reading, so every launch (and graph replay) sees W == 0 on entry.
__device__ float  g_W[COUT * CIN];       // densified fp32 W (kept zeroed)
__device__ __half g_Whi[COUT * CIN];     // fp16 round of W
__device__ __half g_Ahi[MAX_M * CIN];    // fp16 round of x

// ---------------- PTX helpers (vanilla sm_80 features only) ----------------
__device__ __forceinline__ uint32_t smem_u32(const void* p) {
    uint32_t a;
    asm("{ .reg .u64 t; cvta.to.shared.u64 t, %1; cvt.u32.u64 %0, t; }"
        : "=r"(a) : "l"(p));
    return a;
}
__device__ __forceinline__ void cpa16(uint32_t dst, const void* src) {
    asm volatile("cp.async.cg.shared.global [%0], [%1], 16;" :: "r"(dst), "l"(src));
}
__device__ __forceinline__ void cp_commit() {
    asm volatile("cp.async.commit_group;" ::: "memory");
}
template<int N> __device__ __forceinline__ void cp_wait() {
    asm volatile("cp.async.wait_group %0;" :: "n"(N) : "memory");
}
__device__ __forceinline__ void ldsm_x4(uint32_t& r0, uint32_t& r1, uint32_t& r2,
                                        uint32_t& r3, uint32_t addr) {
    asm volatile("ldmatrix.sync.aligned.m8n8.x4.shared.b16 {%0,%1,%2,%3}, [%4];"
                 : "=r"(r0), "=r"(r1), "=r"(r2), "=r"(r3) : "r"(addr));
}
__device__ __forceinline__ void mma_f16(float* c, const uint32_t* a, const uint32_t* b) {
    asm volatile(
        "mma.sync.aligned.m16n8k16.row.col.f32.f16.f16.f32 "
        "{%0,%1,%2,%3}, {%4,%5,%6,%7}, {%8,%9}, {%0,%1,%2,%3};"
        : "+f"(c[0]), "+f"(c[1]), "+f"(c[2]), "+f"(c[3])
        : "r"(a[0]), "r"(a[1]), "r"(a[2]), "r"(a[3]), "r"(b[0]), "r"(b[1]));
}

// pack two float4 into one uint4 of fp16
__device__ __forceinline__ uint4 pack8_f16(float4 v0, float4 v1) {
    __half2 h0 = __float22half2_rn(make_float2(v0.x, v0.y));
    __half2 h1 = __float22half2_rn(make_float2(v0.z, v0.w));
    __half2 h2 = __float22half2_rn(make_float2(v1.x, v1.y));
    __half2 h3 = __float22half2_rn(make_float2(v1.z, v1.w));
    uint4 o;
    o.x = *reinterpret_cast<uint32_t*>(&h0);
    o.y = *reinterpret_cast<uint32_t*>(&h1);
    o.z = *reinterpret_cast<uint32_t*>(&h2);
    o.w = *reinterpret_cast<uint32_t*>(&h3);
    return o;
}

// ---------------- preprocessing ----------------
// K1: blocks [0, ablocks) convert x->fp16 (32 floats/thread, 8 outstanding
// float4 loads -> deep MLP, DRAM-saturating). Blocks [ablocks, ...) do the
// nnz scatter-add into g_W — latency-bound work scheduled LAST so it drains
// inside the conversion's tail.
__global__ void __launch_bounds__(512)
convA_scatter_kernel(const float* __restrict__ x,
                     const float* __restrict__ vals,
                     const int* __restrict__ idx,
                     int nnz, int ablocks, int nA32) {
    if ((int)blockIdx.x >= ablocks) {
        int i = (blockIdx.x - ablocks) * 512 + threadIdx.x;
        if (i < nnz) {
            int r = idx[i];
            int c = idx[nnz + i];
            atomicAdd(&g_W[r * CIN + c], vals[i]);
        }
        return;
    }
    int i = blockIdx.x * 512 + threadIdx.x;
    if (i >= nA32) return;
    const float4* src = reinterpret_cast<const float4*>(x);
    float4 v[8];
#pragma unroll
    for (int t = 0; t < 8; t++) v[t] = src[8 * i + t];   // 8 loads in flight
    uint4* dst = reinterpret_cast<uint4*>(g_Ahi);
#pragma unroll
    for (int t = 0; t < 4; t++)
        dst[4 * i + t] = pack8_f16(v[2 * t], v[2 * t + 1]);
}

// K2: W -> fp16, and re-zero g_W for the next launch/replay.
__global__ void __launch_bounds__(512)
convert_W_kernel() {
    int j = blockIdx.x * 512 + threadIdx.x;    // nW16 threads, 16 floats each
    float4* wsrc = reinterpret_cast<float4*>(g_W);
    float4 v0 = wsrc[4 * j + 0];
    float4 v1 = wsrc[4 * j + 1];
    float4 v2 = wsrc[4 * j + 2];
    float4 v3 = wsrc[4 * j + 3];
    uint4* dst = reinterpret_cast<uint4*>(g_Whi);
    dst[2 * j + 0] = pack8_f16(v0, v1);
    dst[2 * j + 1] = pack8_f16(v2, v3);
    const float4 z = make_float4(0.f, 0.f, 0.f, 0.f);
    wsrc[4 * j + 0] = z;
    wsrc[4 * j + 1] = z;
    wsrc[4 * j + 2] = z;
    wsrc[4 * j + 3] = z;
}

// ---------------- fp16 mma.sync GEMM (R9 config, converged) ----------------
// out[m,n] = sum_k Ahi[m,k] * Whi[n,k]
// BM=BN=128, BK=64. 256 thr = 8 warps in 2(M)x4(N); warp tile 64x32.
// ROWB=144: conflict-free ldmatrix + STS. NSTAGE=3, 110.6KB, 2 CTAs/SM.
#define BK 64
#define ROWB 144
#define TILE_BYTES (128 * ROWB)          // 18432 per operand
#define STAGE_BYTES (2 * TILE_BYTES)     // 36864
#define NSTAGE 3
#define SMEM_TOTAL (NSTAGE * STAGE_BYTES)   // 110592
#define K_ITERS 16                       // 1024 / 64

__global__ void __launch_bounds__(256, 2)
gemm_f16_kernel(float* __restrict__ out) {
    extern __shared__ char smem_raw[];
    const uint32_t sbase = smem_u32(smem_raw);
    const int tid  = threadIdx.x;
    const int lane = tid & 31;
    const int wid  = tid >> 5;
    const int wm   = (wid & 1) * 64;   // warp M offset
    const int wn   = (wid >> 1) * 32;  // warp N offset
    const int m0   = blockIdx.y * 128;
    const int n0   = blockIdx.x * 128;

    float acc[4][4][4];
#pragma unroll
    for (int mi = 0; mi < 4; mi++)
#pragma unroll
        for (int ni = 0; ni < 4; ni++)
#pragma unroll
            for (int q = 0; q < 4; q++) acc[mi][ni][q] = 0.f;

    auto load_stage = [&](int j) {
        const int kk = j * BK;
        const uint32_t aS = sbase + (j % NSTAGE) * STAGE_BYTES;
        const uint32_t bS = aS + TILE_BYTES;
#pragma unroll
        for (int t = 0; t < 4; t++) {
            int c = tid + t * 256;
            int row = c >> 3, kc = c & 7;
            cpa16(aS + row * ROWB + kc * 16,
                  g_Ahi + (size_t)(m0 + row) * CIN + kk + kc * 8);
            cpa16(bS + row * ROWB + kc * 16,
                  g_Whi + (size_t)(n0 + row) * CIN + kk + kc * 8);
        }
        cp_commit();
    };

    auto frag_load = [&](uint32_t aS, uint32_t bS, int ks,
                         uint32_t a[4][4], uint32_t b[4][2]) {
#pragma unroll
        for (int mi = 0; mi < 4; mi++)
            ldsm_x4(a[mi][0], a[mi][1], a[mi][2], a[mi][3],
                    aS + (wm + mi * 16 + (lane & 15)) * ROWB
                       + ks * 32 + (lane >> 4) * 16);
#pragma unroll
        for (int pr = 0; pr < 2; pr++) {
            int t = lane >> 3;
            int row = wn + pr * 16 + ((t >> 1) << 3) + (lane & 7);
            ldsm_x4(b[2 * pr][0], b[2 * pr][1],
                    b[2 * pr + 1][0], b[2 * pr + 1][1],
                    bS + row * ROWB + ks * 32 + (t & 1) * 16);
        }
    };

    load_stage(0);
    load_stage(1);

#pragma unroll 1
    for (int it = 0; it < K_ITERS; it++) {
        if (it == K_ITERS - 1) cp_wait<0>();
        else                   cp_wait<1>();
        __syncthreads();

        const uint32_t aS = sbase + (it % NSTAGE) * STAGE_BYTES;
        const uint32_t bS = aS + TILE_BYTES;

        uint32_t a[4][4], b[4][2];
        frag_load(aS, bS, 0, a, b);
        if (it + 2 < K_ITERS) load_stage(it + 2);
#pragma unroll
        for (int mi = 0; mi < 4; mi++)
#pragma unroll
            for (int ni = 0; ni < 4; ni++)
                mma_f16(acc[mi][ni], a[mi], b[ni]);

#pragma unroll
        for (int ks = 1; ks < 4; ks++) {
            frag_load(aS, bS, ks, a, b);
#pragma unroll
            for (int mi = 0; mi < 4; mi++)
#pragma unroll
                for (int ni = 0; ni < 4; ni++)
                    mma_f16(acc[mi][ni], a[mi], b[ni]);
        }
    }

    // epilogue: direct float2 stores
    const int g = lane >> 2, i2 = (lane & 3) * 2;
#pragma unroll
    for (int mi = 0; mi < 4; mi++) {
        const int row = m0 + wm + mi * 16 + g;
        float* o0 = out + (size_t)row * COUT + n0 + wn;
        float* o1 = o0 + 8 * COUT;
#pragma unroll
        for (int ni = 0; ni < 4; ni++) {
            *reinterpret_cast<float2*>(o0 + ni * 8 + i2) =
                make_float2(acc[mi][ni][0], acc[mi][ni][1]);
            *reinterpret_cast<float2*>(o1 + ni * 8 + i2) =
                make_float2(acc[mi][ni][2], acc[mi][ni][3]);
        }
    }
}

// ---------------- launch ----------------
extern "C" void kernel_launch(void* const* d_in, const int* in_sizes, int n_in,
                              void* d_out, int out_size) {
    const float* x    = (const float*)d_in[0];   // [4, 4096, CIN] fp32
    const float* vals = (const float*)d_in[1];   // [nnz] fp32
    const int*   idx  = (const int*)d_in[2];     // [2, nnz] int32
    float* out = (float*)d_out;                  // [M, COUT] fp32

    const int nnz = in_sizes[1];
    const int M   = in_sizes[0] / CIN;           // 16384

    // K1: A conversion (DRAM-bound, scheduled first) + scatter (latency-
    // bound, scheduled last; g_W is zero on entry).
    const int nA32    = (M * CIN) / 32;          // 524288 threads
    const int ablocks = (nA32 + 511) / 512;      // 1024
    const int sblocks = (nnz + 511) / 512;       // 256
    convA_scatter_kernel<<<ablocks + sblocks, 512>>>(x, vals, idx,
                                                     nnz, ablocks, nA32);
    // K2: W -> fp16 (+ re-zero g_W for next replay)
    const int nW16 = (COUT * CIN) / 16;
    convert_W_kernel<<<nW16 / 512, 512>>>();

    static int smem_set = 0;
    if (!smem_set) {
        cudaFuncSetAttribute(gemm_f16_kernel,
                             cudaFuncAttributeMaxDynamicSharedMemorySize, SMEM_TOTAL);
        smem_set = 1;
    }
    dim3 grid(COUT / 128, M / 128);   // x = n fastest -> wave shares W tiles in L2
    gemm_f16_kernel<<<grid, 256, SMEM_TOTAL>>>(out);
}

// round 16
// speedup vs baseline: 1.0089x; 1.0089x over previous
#include <cuda_runtime.h>
#include <cuda_fp16.h>
#include <cstdint>

#define CIN  1024
#define COUT 1024
#define MAX_M 16384

// ---------------- device global scratch (allocation-free) ----------------
// g_W is zero-initialized at module load; convert_W_kernel re-zeroes it
// after reading, so every launch (and graph replay) sees W == 0 on entry.
__device__ float  g_W[COUT * CIN];       // densified fp32 W (kept zeroed)
__device__ __half g_Whi[COUT * CIN];     // fp16 round of W
__device__ __half g_Ahi[MAX_M * CIN];    // fp16 round of x

// ---------------- PTX helpers (vanilla sm_80 features only) ----------------
__device__ __forceinline__ uint32_t smem_u32(const void* p) {
    uint32_t a;
    asm("{ .reg .u64 t; cvta.to.shared.u64 t, %1; cvt.u32.u64 %0, t; }"
        : "=r"(a) : "l"(p));
    return a;
}
__device__ __forceinline__ void cpa16(uint32_t dst, const void* src) {
    asm volatile("cp.async.cg.shared.global [%0], [%1], 16;" :: "r"(dst), "l"(src));
}
__device__ __forceinline__ void cp_commit() {
    asm volatile("cp.async.commit_group;" ::: "memory");
}
template<int N> __device__ __forceinline__ void cp_wait() {
    asm volatile("cp.async.wait_group %0;" :: "n"(N) : "memory");
}
__device__ __forceinline__ void ldsm_x4(uint32_t& r0, uint32_t& r1, uint32_t& r2,
                                        uint32_t& r3, uint32_t addr) {
    asm volatile("ldmatrix.sync.aligned.m8n8.x4.shared.b16 {%0,%1,%2,%3}, [%4];"
                 : "=r"(r0), "=r"(r1), "=r"(r2), "=r"(r3) : "r"(addr));
}
__device__ __forceinline__ void mma_f16(float* c, const uint32_t* a, const uint32_t* b) {
    asm volatile(
        "mma.sync.aligned.m16n8k16.row.col.f32.f16.f16.f32 "
        "{%0,%1,%2,%3}, {%4,%5,%6,%7}, {%8,%9}, {%0,%1,%2,%3};"
        : "+f"(c[0]), "+f"(c[1]), "+f"(c[2]), "+f"(c[3])
        : "r"(a[0]), "r"(a[1]), "r"(a[2]), "r"(a[3]), "r"(b[0]), "r"(b[1]));
}

// pack two float4 into one uint4 of fp16
__device__ __forceinline__ uint4 pack8_f16(float4 v0, float4 v1) {
    __half2 h0 = __float22half2_rn(make_float2(v0.x, v0.y));
    __half2 h1 = __float22half2_rn(make_float2(v0.z, v0.w));
    __half2 h2 = __float22half2_rn(make_float2(v1.x, v1.y));
    __half2 h3 = __float22half2_rn(make_float2(v1.z, v1.w));
    uint4 o;
    o.x = *reinterpret_cast<uint32_t*>(&h0);
    o.y = *reinterpret_cast<uint32_t*>(&h1);
    o.z = *reinterpret_cast<uint32_t*>(&h2);
    o.w = *reinterpret_cast<uint32_t*>(&h3);
    return o;
}

// ---------------- preprocessing ----------------
// Branch A (main stream): x -> fp16, 16 floats/thread (R14-proven form).
__global__ void __launch_bounds__(512)
convert_A_kernel(const float* __restrict__ x, int nA16) {
    int i = blockIdx.x * 512 + threadIdx.x;
    if (i >= nA16) return;
    const float4* src = reinterpret_cast<const float4*>(x);
    float4 v0 = src[4 * i + 0];
    float4 v1 = src[4 * i + 1];
    float4 v2 = src[4 * i + 2];
    float4 v3 = src[4 * i + 3];
    uint4* dst = reinterpret_cast<uint4*>(g_Ahi);
    dst[2 * i + 0] = pack8_f16(v0, v1);
    dst[2 * i + 1] = pack8_f16(v2, v3);
}

// Branch B (side stream): scatter-add into g_W (zero on entry) ...
__global__ void __launch_bounds__(512)
scatter_W_kernel(const float* __restrict__ vals,
                 const int* __restrict__ idx, int nnz) {
    int i = blockIdx.x * 512 + threadIdx.x;
    if (i < nnz) {
        int r = idx[i];
        int c = idx[nnz + i];
        atomicAdd(&g_W[r * CIN + c], vals[i]);
    }
}

// ... then W -> fp16, re-zeroing g_W for the next launch/replay.
__global__ void __launch_bounds__(512)
convert_W_kernel() {
    int j = blockIdx.x * 512 + threadIdx.x;    // nW16 threads, 16 floats each
    float4* wsrc = reinterpret_cast<float4*>(g_W);
    float4 v0 = wsrc[4 * j + 0];
    float4 v1 = wsrc[4 * j + 1];
    float4 v2 = wsrc[4 * j + 2];
    float4 v3 = wsrc[4 * j + 3];
    uint4* dst = reinterpret_cast<uint4*>(g_Whi);
    dst[2 * j + 0] = pack8_f16(v0, v1);
    dst[2 * j + 1] = pack8_f16(v2, v3);
    const float4 z = make_float4(0.f, 0.f, 0.f, 0.f);
    wsrc[4 * j + 0] = z;
    wsrc[4 * j + 1] = z;
    wsrc[4 * j + 2] = z;
    wsrc[4 * j + 3] = z;
}

// ---------------- fp16 mma.sync GEMM (R9 config, converged) ----------------
// out[m,n] = sum_k Ahi[m,k] * Whi[n,k]
// BM=BN=128, BK=64. 256 thr = 8 warps in 2(M)x4(N); warp tile 64x32.
// ROWB=144: conflict-free ldmatrix + STS. NSTAGE=3, 110.6KB, 2 CTAs/SM.
#define BK 64
#define ROWB 144
#define TILE_BYTES (128 * ROWB)          // 18432 per operand
#define STAGE_BYTES (2 * TILE_BYTES)     // 36864
#define NSTAGE 3
#define SMEM_TOTAL (NSTAGE * STAGE_BYTES)   // 110592
#define K_ITERS 16                       // 1024 / 64

__global__ void __launch_bounds__(256, 2)
gemm_f16_kernel(float* __restrict__ out) {
    extern __shared__ char smem_raw[];
    const uint32_t sbase = smem_u32(smem_raw);
    const int tid  = threadIdx.x;
    const int lane = tid & 31;
    const int wid  = tid >> 5;
    const int wm   = (wid & 1) * 64;   // warp M offset
    const int wn   = (wid >> 1) * 32;  // warp N offset
    const int m0   = blockIdx.y * 128;
    const int n0   = blockIdx.x * 128;

    float acc[4][4][4];
#pragma unroll
    for (int mi = 0; mi < 4; mi++)
#pragma unroll
        for (int ni = 0; ni < 4; ni++)
#pragma unroll
            for (int q = 0; q < 4; q++) acc[mi][ni][q] = 0.f;

    auto load_stage = [&](int j) {
        const int kk = j * BK;
        const uint32_t aS = sbase + (j % NSTAGE) * STAGE_BYTES;
        const uint32_t bS = aS + TILE_BYTES;
#pragma unroll
        for (int t = 0; t < 4; t++) {
            int c = tid + t * 256;
            int row = c >> 3, kc = c & 7;
            cpa16(aS + row * ROWB + kc * 16,
                  g_Ahi + (size_t)(m0 + row) * CIN + kk + kc * 8);
            cpa16(bS + row * ROWB + kc * 16,
                  g_Whi + (size_t)(n0 + row) * CIN + kk + kc * 8);
        }
        cp_commit();
    };

    auto frag_load = [&](uint32_t aS, uint32_t bS, int ks,
                         uint32_t a[4][4], uint32_t b[4][2]) {
#pragma unroll
        for (int mi = 0; mi < 4; mi++)
            ldsm_x4(a[mi][0], a[mi][1], a[mi][2], a[mi][3],
                    aS + (wm + mi * 16 + (lane & 15)) * ROWB
                       + ks * 32 + (lane >> 4) * 16);
#pragma unroll
        for (int pr = 0; pr < 2; pr++) {
            int t = lane >> 3;
            int row = wn + pr * 16 + ((t >> 1) << 3) + (lane & 7);
            ldsm_x4(b[2 * pr][0], b[2 * pr][1],
                    b[2 * pr + 1][0], b[2 * pr + 1][1],
                    bS + row * ROWB + ks * 32 + (t & 1) * 16);
        }
    };

    load_stage(0);
    load_stage(1);

#pragma unroll 1
    for (int it = 0; it < K_ITERS; it++) {
        if (it == K_ITERS - 1) cp_wait<0>();
        else                   cp_wait<1>();
        __syncthreads();

        const uint32_t aS = sbase + (it % NSTAGE) * STAGE_BYTES;
        const uint32_t bS = aS + TILE_BYTES;

        uint32_t a[4][4], b[4][2];
        frag_load(aS, bS, 0, a, b);
        if (it + 2 < K_ITERS) load_stage(it + 2);
#pragma unroll
        for (int mi = 0; mi < 4; mi++)
#pragma unroll
            for (int ni = 0; ni < 4; ni++)
                mma_f16(acc[mi][ni], a[mi], b[ni]);

#pragma unroll
        for (int ks = 1; ks < 4; ks++) {
            frag_load(aS, bS, ks, a, b);
#pragma unroll
            for (int mi = 0; mi < 4; mi++)
#pragma unroll
                for (int ni = 0; ni < 4; ni++)
                    mma_f16(acc[mi][ni], a[mi], b[ni]);
        }
    }

    // epilogue: direct float2 stores
    const int g = lane >> 2, i2 = (lane & 3) * 2;
#pragma unroll
    for (int mi = 0; mi < 4; mi++) {
        const int row = m0 + wm + mi * 16 + g;
        float* o0 = out + (size_t)row * COUT + n0 + wn;
        float* o1 = o0 + 8 * COUT;
#pragma unroll
        for (int ni = 0; ni < 4; ni++) {
            *reinterpret_cast<float2*>(o0 + ni * 8 + i2) =
                make_float2(acc[mi][ni][0], acc[mi][ni][1]);
            *reinterpret_cast<float2*>(o1 + ni * 8 + i2) =
                make_float2(acc[mi][ni][2], acc[mi][ni][3]);
        }
    }
}

// ---------------- launch ----------------
// Graph shape:  (legacy) --fork--> [scatter -> convertW]  (side stream)
//               (legacy) [convA] ----------join----------> [GEMM]
// The W-chain (~8us) hides entirely under convA (~16us).
extern "C" void kernel_launch(void* const* d_in, const int* in_sizes, int n_in,
                              void* d_out, int out_size) {
    const float* x    = (const float*)d_in[0];   // [4, 4096, CIN] fp32
    const float* vals = (const float*)d_in[1];   // [nnz] fp32
    const int*   idx  = (const int*)d_in[2];     // [2, nnz] int32
    float* out = (float*)d_out;                  // [M, COUT] fp32

    const int nnz = in_sizes[1];
    const int M   = in_sizes[0] / CIN;           // 16384

    static cudaStream_t s2 = nullptr;
    static cudaEvent_t evFork = nullptr, evJoin = nullptr;
    if (s2 == nullptr) {
        cudaStreamCreateWithFlags(&s2, cudaStreamNonBlocking);
        cudaEventCreateWithFlags(&evFork, cudaEventDisableTiming);
        cudaEventCreateWithFlags(&evJoin, cudaEventDisableTiming);
        cudaFuncSetAttribute(gemm_f16_kernel,
                             cudaFuncAttributeMaxDynamicSharedMemorySize, SMEM_TOTAL);
    }

    // fork: side stream depends on capture-stream head
    cudaEventRecord(evFork, 0);
    cudaStreamWaitEvent(s2, evFork, 0);

    // branch B (side stream): scatter into g_W (zero on entry), then W->fp16
    const int sblocks = (nnz + 511) / 512;       // 256
    scatter_W_kernel<<<sblocks, 512, 0, s2>>>(vals, idx, nnz);
    const int nW16 = (COUT * CIN) / 16;
    convert_W_kernel<<<nW16 / 512, 512, 0, s2>>>();

    // branch A (legacy stream): x -> fp16
    const int nA16 = (M * CIN) / 16;
    convert_A_kernel<<<(nA16 + 511) / 512, 512>>>(x, nA16);

    // join: GEMM needs both g_Ahi (branch A) and g_Whi (branch B)
    cudaEventRecord(evJoin, s2);
    cudaStreamWaitEvent(0, evJoin, 0);

    dim3 grid(COUT / 128, M / 128);   // x = n fastest -> wave shares W tiles in L2
    gemm_f16_kernel<<<grid, 256, SMEM_TOTAL>>>(out);
}

// round 17
// speedup vs baseline: 1.0484x; 1.0392x over previous
#include <cuda_runtime.h>
#include <cuda_fp16.h>
#include <cstdint>

#define CIN  1024
#define COUT 1024
#define MAX_M 16384

// ---------------- device global scratch (allocation-free) ----------------
// g_Whi is zero-initialized at module load; zero_Whi_kernel (run after the
// GEMM each call) re-zeroes it, so every launch/replay scatters into zeros.
__device__ __half g_Whi[COUT * CIN];     // fp16 W, built directly by atomics
__device__ __half g_Ahi[MAX_M * CIN];    // fp16 round of x

// ---------------- PTX helpers (vanilla sm_80 features only) ----------------
__device__ __forceinline__ uint32_t smem_u32(const void* p) {
    uint32_t a;
    asm("{ .reg .u64 t; cvta.to.shared.u64 t, %1; cvt.u32.u64 %0, t; }"
        : "=r"(a) : "l"(p));
    return a;
}
__device__ __forceinline__ void cpa16(uint32_t dst, const void* src) {
    asm volatile("cp.async.cg.shared.global [%0], [%1], 16;" :: "r"(dst), "l"(src));
}
__device__ __forceinline__ void cp_commit() {
    asm volatile("cp.async.commit_group;" ::: "memory");
}
template<int N> __device__ __forceinline__ void cp_wait() {
    asm volatile("cp.async.wait_group %0;" :: "n"(N) : "memory");
}
__device__ __forceinline__ void ldsm_x4(uint32_t& r0, uint32_t& r1, uint32_t& r2,
                                        uint32_t& r3, uint32_t addr) {
    asm volatile("ldmatrix.sync.aligned.m8n8.x4.shared.b16 {%0,%1,%2,%3}, [%4];"
                 : "=r"(r0), "=r"(r1), "=r"(r2), "=r"(r3) : "r"(addr));
}
__device__ __forceinline__ void mma_f16(float* c, const uint32_t* a, const uint32_t* b) {
    asm volatile(
        "mma.sync.aligned.m16n8k16.row.col.f32.f16.f16.f32 "
        "{%0,%1,%2,%3}, {%4,%5,%6,%7}, {%8,%9}, {%0,%1,%2,%3};"
        : "+f"(c[0]), "+f"(c[1]), "+f"(c[2]), "+f"(c[3])
        : "r"(a[0]), "r"(a[1]), "r"(a[2]), "r"(a[3]), "r"(b[0]), "r"(b[1]));
}

// pack two float4 into one uint4 of fp16
__device__ __forceinline__ uint4 pack8_f16(float4 v0, float4 v1) {
    __half2 h0 = __float22half2_rn(make_float2(v0.x, v0.y));
    __half2 h1 = __float22half2_rn(make_float2(v0.z, v0.w));
    __half2 h2 = __float22half2_rn(make_float2(v1.x, v1.y));
    __half2 h3 = __float22half2_rn(make_float2(v1.z, v1.w));
    uint4 o;
    o.x = *reinterpret_cast<uint32_t*>(&h0);
    o.y = *reinterpret_cast<uint32_t*>(&h1);
    o.z = *reinterpret_cast<uint32_t*>(&h2);
    o.w = *reinterpret_cast<uint32_t*>(&h3);
    return o;
}

// ---------------- preprocessing ----------------
// K1 (fused, R14-proven layout): blocks [0, sblocks) scatter fp16 atomics
// directly into g_Whi (latency-bound; hides under the conversion);
// blocks [sblocks, ...) convert x -> fp16, 16 floats/thread.
// fp16-atomic precision: untouched/unique slots are bit-identical to
// densify-then-round; only duplicate (row,col) slots (~0.7%) accumulate one
// extra rounding — negligible vs the 1e-3 budget.
__global__ void __launch_bounds__(512)
scatter_convA_kernel(const float* __restrict__ x,
                     const float* __restrict__ vals,
                     const int* __restrict__ idx,
                     int nnz, int sblocks, int nA16) {
    if ((int)blockIdx.x < sblocks) {
        int i = blockIdx.x * 512 + threadIdx.x;
        if (i < nnz) {
            int r = idx[i];
            int c = idx[nnz + i];
            atomicAdd(&g_Whi[r * CIN + c], __float2half_rn(vals[i]));
        }
        return;
    }
    int i = (blockIdx.x - sblocks) * 512 + threadIdx.x;
    if (i >= nA16) return;
    const float4* src = reinterpret_cast<const float4*>(x);
    float4 v0 = src[4 * i + 0];
    float4 v1 = src[4 * i + 1];
    float4 v2 = src[4 * i + 2];
    float4 v3 = src[4 * i + 3];
    uint4* dst = reinterpret_cast<uint4*>(g_Ahi);
    dst[2 * i + 0] = pack8_f16(v0, v1);
    dst[2 * i + 1] = pack8_f16(v2, v3);
}

// K3 (trailing): re-zero g_Whi so the next launch/replay scatters into zeros.
__global__ void __launch_bounds__(512)
zero_Whi_kernel() {
    int i = blockIdx.x * 512 + threadIdx.x;    // COUT*CIN/8 threads
    reinterpret_cast<uint4*>(g_Whi)[i] = make_uint4(0u, 0u, 0u, 0u);
}

// ---------------- fp16 mma.sync GEMM (R9 config, converged) ----------------
// out[m,n] = sum_k Ahi[m,k] * Whi[n,k]
// BM=BN=128, BK=64. 256 thr = 8 warps in 2(M)x4(N); warp tile 64x32.
// ROWB=144: conflict-free ldmatrix + STS. NSTAGE=3, 110.6KB, 2 CTAs/SM.
#define BK 64
#define ROWB 144
#define TILE_BYTES (128 * ROWB)          // 18432 per operand
#define STAGE_BYTES (2 * TILE_BYTES)     // 36864
#define NSTAGE 3
#define SMEM_TOTAL (NSTAGE * STAGE_BYTES)   // 110592
#define K_ITERS 16                       // 1024 / 64

__global__ void __launch_bounds__(256, 2)
gemm_f16_kernel(float* __restrict__ out) {
    extern __shared__ char smem_raw[];
    const uint32_t sbase = smem_u32(smem_raw);
    const int tid  = threadIdx.x;
    const int lane = tid & 31;
    const int wid  = tid >> 5;
    const int wm   = (wid & 1) * 64;   // warp M offset
    const int wn   = (wid >> 1) * 32;  // warp N offset
    const int m0   = blockIdx.y * 128;
    const int n0   = blockIdx.x * 128;

    float acc[4][4][4];
#pragma unroll
    for (int mi = 0; mi < 4; mi++)
#pragma unroll
        for (int ni = 0; ni < 4; ni++)
#pragma unroll
            for (int q = 0; q < 4; q++) acc[mi][ni][q] = 0.f;

    auto load_stage = [&](int j) {
        const int kk = j * BK;
        const uint32_t aS = sbase + (j % NSTAGE) * STAGE_BYTES;
        const uint32_t bS = aS + TILE_BYTES;
#pragma unroll
        for (int t = 0; t < 4; t++) {
            int c = tid + t * 256;
            int row = c >> 3, kc = c & 7;
            cpa16(aS + row * ROWB + kc * 16,
                  g_Ahi + (size_t)(m0 + row) * CIN + kk + kc * 8);
            cpa16(bS + row * ROWB + kc * 16,
                  g_Whi + (size_t)(n0 + row) * CIN + kk + kc * 8);
        }
        cp_commit();
    };

    auto frag_load = [&](uint32_t aS, uint32_t bS, int ks,
                         uint32_t a[4][4], uint32_t b[4][2]) {
#pragma unroll
        for (int mi = 0; mi < 4; mi++)
            ldsm_x4(a[mi][0], a[mi][1], a[mi][2], a[mi][3],
                    aS + (wm + mi * 16 + (lane & 15)) * ROWB
                       + ks * 32 + (lane >> 4) * 16);
#pragma unroll
        for (int pr = 0; pr < 2; pr++) {
            int t = lane >> 3;
            int row = wn + pr * 16 + ((t >> 1) << 3) + (lane & 7);
            ldsm_x4(b[2 * pr][0], b[2 * pr][1],
                    b[2 * pr + 1][0], b[2 * pr + 1][1],
                    bS + row * ROWB + ks * 32 + (t & 1) * 16);
        }
    };

    load_stage(0);
    load_stage(1);

#pragma unroll 1
    for (int it = 0; it < K_ITERS; it++) {
        if (it == K_ITERS - 1) cp_wait<0>();
        else                   cp_wait<1>();
        __syncthreads();

        const uint32_t aS = sbase + (it % NSTAGE) * STAGE_BYTES;
        const uint32_t bS = aS + TILE_BYTES;

        uint32_t a[4][4], b[4][2];
        frag_load(aS, bS, 0, a, b);
        if (it + 2 < K_ITERS) load_stage(it + 2);
#pragma unroll
        for (int mi = 0; mi < 4; mi++)
#pragma unroll
            for (int ni = 0; ni < 4; ni++)
                mma_f16(acc[mi][ni], a[mi], b[ni]);

#pragma unroll
        for (int ks = 1; ks < 4; ks++) {
            frag_load(aS, bS, ks, a, b);
#pragma unroll
            for (int mi = 0; mi < 4; mi++)
#pragma unroll
                for (int ni = 0; ni < 4; ni++)
                    mma_f16(acc[mi][ni], a[mi], b[ni]);
        }
    }

    // epilogue: direct float2 stores
    const int g = lane >> 2, i2 = (lane & 3) * 2;
#pragma unroll
    for (int mi = 0; mi < 4; mi++) {
        const int row = m0 + wm + mi * 16 + g;
        float* o0 = out + (size_t)row * COUT + n0 + wn;
        float* o1 = o0 + 8 * COUT;
#pragma unroll
        for (int ni = 0; ni < 4; ni++) {
            *reinterpret_cast<float2*>(o0 + ni * 8 + i2) =
                make_float2(acc[mi][ni][0], acc[mi][ni][1]);
            *reinterpret_cast<float2*>(o1 + ni * 8 + i2) =
                make_float2(acc[mi][ni][2], acc[mi][ni][3]);
        }
    }
}

// ---------------- launch ----------------
// K1: fused fp16-scatter (into zeroed g_Whi) + A conversion
// K2: GEMM
// K3: re-zero g_Whi for the next launch / graph replay
extern "C" void kernel_launch(void* const* d_in, const int* in_sizes, int n_in,
                              void* d_out, int out_size) {
    const float* x    = (const float*)d_in[0];   // [4, 4096, CIN] fp32
    const float* vals = (const float*)d_in[1];   // [nnz] fp32
    const int*   idx  = (const int*)d_in[2];     // [2, nnz] int32
    float* out = (float*)d_out;                  // [M, COUT] fp32

    const int nnz = in_sizes[1];
    const int M   = in_sizes[0] / CIN;           // 16384

    const int nA16    = (M * CIN) / 16;          // 1048576
    const int sblocks = (nnz + 511) / 512;       // 256
    const int ablocks = (nA16 + 511) / 512;      // 2048
    scatter_convA_kernel<<<sblocks + ablocks, 512>>>(x, vals, idx,
                                                     nnz, sblocks, nA16);

    static int smem_set = 0;
    if (!smem_set) {
        cudaFuncSetAttribute(gemm_f16_kernel,
                             cudaFuncAttributeMaxDynamicSharedMemorySize, SMEM_TOTAL);
        smem_set = 1;
    }
    dim3 grid(COUT / 128, M / 128);   // x = n fastest -> wave shares W tiles in L2
    gemm_f16_kernel<<<grid, 256, SMEM_TOTAL>>>(out);

    zero_Whi_kernel<<<(COUT * CIN / 8) / 512, 512>>>();
}